// round 10
// baseline (speedup 1.0000x reference)
#include <cuda_runtime.h>
#include <cuda_fp16.h>
#include <cstdint>

// ThreeBodyLayer — round 10: fp16 MMA everywhere (8x precision of bf16),
// core projection folded into the CA GEMM (K=128), uniform 24-unit phase 1,
// 256-thr CTAs x2/SM (16 warps/SM), phase-2 as 2 sequential M=16 chunks.
//
// Phase 1: 24 units (k=lig 0..5, np=n-tile 0..3), 3 per warp. Unit =
//   CA part: [16 rows]x[K=128: lig_k|core] @ W1A^T (n16) -> CA_k (+b1),
//   B  part: [16 rows]x[K=64: lig_k] @ W1B^T (n16) -> B_k.
//   x fp16 (single), W1 fp16 hi+lo (2-product). C -> cab[16][12][64 f32].
// Phase 2: warp w rows {2w,2w+1}; chunk c: 16 ordered pairs (q=c*16+..),
//   h = softplus(CA_i + B_j) -> fp16 (single) -> 2KB/warp buffer;
//   16 MMAs vs register W2-fp16 frags; epilogue softplus(t+b2)@W3 masked.

#define FULLMASK 0xFFFFFFFFu

__device__ __forceinline__ float softplus_f(float x) {
    return fmaxf(x, 0.0f) + __logf(1.0f + __expf(-fabsf(x)));
}
__device__ __forceinline__ uint32_t smem_u32(const void* p) {
    uint32_t a;
    asm("{ .reg .u64 t; cvta.to.shared.u64 t, %1; cvt.u32.u64 %0, t; }"
        : "=r"(a) : "l"(p));
    return a;
}
__device__ __forceinline__ uint32_t pkhf(float a, float b) {   // hi=a, lo=b
    uint32_t r; asm("cvt.rn.f16x2.f32 %0, %1, %2;" : "=r"(r) : "f"(a), "f"(b));
    return r;
}
__device__ __forceinline__ void ldsm4(uint32_t* r, uint32_t addr) {
    asm volatile("ldmatrix.sync.aligned.m8n8.x4.shared.b16 {%0,%1,%2,%3}, [%4];"
                 : "=r"(r[0]), "=r"(r[1]), "=r"(r[2]), "=r"(r[3]) : "r"(addr));
}
__device__ __forceinline__ void mma_f16(float* c, const uint32_t* a,
                                        uint32_t b0, uint32_t b1) {
    asm volatile(
        "mma.sync.aligned.m16n8k16.row.col.f32.f16.f16.f32 "
        "{%0,%1,%2,%3}, {%4,%5,%6,%7}, {%8,%9}, {%0,%1,%2,%3};"
        : "+f"(c[0]), "+f"(c[1]), "+f"(c[2]), "+f"(c[3])
        : "r"(a[0]), "r"(a[1]), "r"(a[2]), "r"(a[3]), "r"(b0), "r"(b1));
}

// ---- SMEM layout (bytes) per 256-thread CTA ----
// W1A: [64 n][128 k] fp16 (k<64: W1[64+k][n] lig-A; k>=64: W1[k-64][n] core),
//      256B rows, chunk xor ((n&7)<<4). Hi + lo-residual tables.
// W1B: [64 n][64 k] fp16 (W1[128+k][n]), 128B rows, same swizzle. Hi + lo.
// cab: [16 rows][12 vecs][64 f32]; addr = row*3072 + vec*256 +
//      (d4 ^ ((vec&7)<<4) ^ ((row&7)<<5)).  vec 0..5 = CA_k (incl cp+b1),
//      6..11 = B_k.
// h:   [8 warps][16 pair-rows][64 fp16], 128B rows, chunk xor ((p&7)<<4).
static constexpr int S_W1AH = 0;        // 16384
static constexpr int S_W1AL = 16384;    // 16384
static constexpr int S_W1BH = 32768;    // 8192
static constexpr int S_W1BL = 40960;    // 8192
static constexpr int S_CAB  = 49152;    // 49152
static constexpr int S_H    = 98304;    // 16384
static constexpr int SMEM_BYTES = 114688;

__global__ void __launch_bounds__(256, 2) three_body_kernel(
    const float* __restrict__ core,   // [B, 64]
    const float* __restrict__ ligs,   // [B, 6, 64]
    const float* __restrict__ W1,     // [192, 64]
    const float* __restrict__ b1,     // [64]
    const float* __restrict__ W2,     // [64, 32]
    const float* __restrict__ b2,     // [32]
    const float* __restrict__ W3,     // [32]
    const float* __restrict__ b3,     // [1]
    float* __restrict__ out,          // [B]
    int B)
{
    extern __shared__ unsigned char sm[];
    const uint32_t smb = smem_u32(sm);
    const int tid  = threadIdx.x;
    const int lane = tid & 31;
    const int wid  = tid >> 5;        // 0..7

    // ---- stage W1A (hi/lo, fp16, 256B swizzled rows) ----
    for (int idx = tid; idx < 8192; idx += 256) {
        int n = idx >> 7, k = idx & 127;
        float w = (k < 64) ? W1[(64 + k) * 64 + n] : W1[(k - 64) * 64 + n];
        __half h = __float2half_rn(w);
        float res = w - __half2float(h);
        int byte = n * 256 + ((2 * k) ^ ((n & 7) << 4));
        *reinterpret_cast<__half*>(sm + S_W1AH + byte) = h;
        *reinterpret_cast<__half*>(sm + S_W1AL + byte) = __float2half_rn(res);
    }
    // ---- stage W1B (hi/lo, fp16, 128B swizzled rows) ----
    for (int idx = tid; idx < 4096; idx += 256) {
        int n = idx >> 6, k = idx & 63;
        float w = W1[(128 + k) * 64 + n];
        __half h = __float2half_rn(w);
        float res = w - __half2float(h);
        int byte = n * 128 + ((2 * k) ^ ((n & 7) << 4));
        *reinterpret_cast<__half*>(sm + S_W1BH + byte) = h;
        *reinterpret_cast<__half*>(sm + S_W1BL + byte) = __float2half_rn(res);
    }

    // ---- W2 fragments in registers (fp16, single product) ----
    uint32_t B1f[4][4][2];
    {
        const int krow = (lane & 3) * 2;
        const int ncol = lane >> 2;
        #pragma unroll
        for (int kt = 0; kt < 4; kt++)
            #pragma unroll
            for (int nt = 0; nt < 4; nt++) {
                int k0 = kt * 16 + krow, n = nt * 8 + ncol;
                B1f[kt][nt][0] = pkhf(W2[(k0 + 1) * 32 + n], W2[(k0 + 0) * 32 + n]);
                B1f[kt][nt][1] = pkhf(W2[(k0 + 9) * 32 + n], W2[(k0 + 8) * 32 + n]);
            }
    }

    const float b3v = b3[0];
    const int r0  = lane >> 2;            // frag row (0..7)
    const int c0  = (lane & 3) * 2;       // frag col pair base
    const uint32_t csel = (uint32_t)(lane >> 4) * 16;
    const uint32_t p15  = (uint32_t)(lane & 15);
    const uint32_t psw  = (uint32_t)(lane & 7) << 4;
    const uint32_t hwarp = smb + S_H + (uint32_t)wid * 2048;
    char* hp = (char*)sm + S_H + wid * 2048 + (lane & 15) * 128;

    const int n_groups = B >> 4;   // 2048

    __syncthreads();

    for (int g = blockIdx.x; g < n_groups; g += gridDim.x) {
        const int rbase = g << 4;
        __syncthreads();   // previous group's phase-2 cab reads complete

        // ================= phase 1: 3 uniform units per warp =================
        #pragma unroll
        for (int t = 0; t < 3; t++) {
            const int uid = wid * 3 + t;           // 0..23
            const int k  = uid >> 2;               // ligand
            const int np = uid & 3;                // n-tile

            // A-fragments: rows rbase+r0 / +8; K=128 = [lig_k | core]
            const float* la = ligs + (size_t)(rbase + r0) * 384 + k * 64 + c0;
            const float* lb = ligs + (size_t)(rbase + r0 + 8) * 384 + k * 64 + c0;
            const float* ca = core + (size_t)(rbase + r0) * 64 + c0;
            const float* cb = core + (size_t)(rbase + r0 + 8) * 64 + c0;
            uint32_t af[8][4];
            #pragma unroll
            for (int kt = 0; kt < 8; kt++) {
                const float* pa = (kt < 4) ? la + kt * 16 : ca + (kt - 4) * 16;
                const float* pb = (kt < 4) ? lb + kt * 16 : cb + (kt - 4) * 16;
                float2 x00 = *reinterpret_cast<const float2*>(pa);
                float2 x10 = *reinterpret_cast<const float2*>(pb);
                float2 x01 = *reinterpret_cast<const float2*>(pa + 8);
                float2 x11 = *reinterpret_cast<const float2*>(pb + 8);
                af[kt][0] = pkhf(x00.y, x00.x);  af[kt][1] = pkhf(x10.y, x10.x);
                af[kt][2] = pkhf(x01.y, x01.x);  af[kt][3] = pkhf(x11.y, x11.x);
            }

            const uint32_t n   = (uint32_t)np * 16 + p15;   // W1 table row
            const uint32_t nsw = (n & 7) << 4;

            // --- CA unit: K=128, W1A hi+lo ---
            {
                float a0[4] = {0.f, 0.f, 0.f, 0.f}, a1[4] = {0.f, 0.f, 0.f, 0.f};
                #pragma unroll
                for (int kt = 0; kt < 8; kt++) {
                    uint32_t bh[4], bl[4];
                    uint32_t adr = smb + S_W1AH + n * 256
                                 + (((uint32_t)kt * 32 + csel) ^ nsw);
                    ldsm4(bh, adr);
                    ldsm4(bl, adr + (S_W1AL - S_W1AH));
                    mma_f16(a0, af[kt], bh[0], bh[2]);
                    mma_f16(a0, af[kt], bl[0], bl[2]);
                    mma_f16(a1, af[kt], bh[1], bh[3]);
                    mma_f16(a1, af[kt], bl[1], bl[3]);
                }
                #pragma unroll
                for (int ntl = 0; ntl < 2; ntl++) {
                    const float* a = ntl ? a1 : a0;
                    int d = np * 16 + ntl * 8 + c0;
                    float bb0 = __ldg(b1 + d), bb1 = __ldg(b1 + d + 1);
                    uint32_t db = (uint32_t)(d * 4) ^ ((uint32_t)(k & 7) << 4);
                    char* q0 = (char*)sm + S_CAB + r0 * 3072 + k * 256
                             + (db ^ ((uint32_t)(r0 & 7) << 5));
                    char* q1 = (char*)sm + S_CAB + (r0 + 8) * 3072 + k * 256
                             + (db ^ ((uint32_t)(r0 & 7) << 5));
                    *reinterpret_cast<float2*>(q0) = make_float2(a[0] + bb0, a[1] + bb1);
                    *reinterpret_cast<float2*>(q1) = make_float2(a[2] + bb0, a[3] + bb1);
                }
            }
            // --- B unit: K=64 (lig only), W1B hi+lo ---
            {
                float a0[4] = {0.f, 0.f, 0.f, 0.f}, a1[4] = {0.f, 0.f, 0.f, 0.f};
                #pragma unroll
                for (int kt = 0; kt < 4; kt++) {
                    uint32_t bh[4], bl[4];
                    uint32_t adr = smb + S_W1BH + n * 128
                                 + (((uint32_t)kt * 32 + csel) ^ nsw);
                    ldsm4(bh, adr);
                    ldsm4(bl, adr + (S_W1BL - S_W1BH));
                    mma_f16(a0, af[kt], bh[0], bh[2]);
                    mma_f16(a0, af[kt], bl[0], bl[2]);
                    mma_f16(a1, af[kt], bh[1], bh[3]);
                    mma_f16(a1, af[kt], bl[1], bl[3]);
                }
                const int vec = 6 + k;
                #pragma unroll
                for (int ntl = 0; ntl < 2; ntl++) {
                    const float* a = ntl ? a1 : a0;
                    int d = np * 16 + ntl * 8 + c0;
                    uint32_t db = (uint32_t)(d * 4) ^ ((uint32_t)(vec & 7) << 4);
                    char* q0 = (char*)sm + S_CAB + r0 * 3072 + vec * 256
                             + (db ^ ((uint32_t)(r0 & 7) << 5));
                    char* q1 = (char*)sm + S_CAB + (r0 + 8) * 3072 + vec * 256
                             + (db ^ ((uint32_t)(r0 & 7) << 5));
                    *reinterpret_cast<float2*>(q0) = make_float2(a[0], a[1]);
                    *reinterpret_cast<float2*>(q1) = make_float2(a[2], a[3]);
                }
            }
        }
        __syncthreads();   // cab complete

        // ================= phase 2: 2 rows/warp, 2 M=16 chunks each =================
        #pragma unroll
        for (int rr = 0; rr < 2; rr++) {
            const int row = wid * 2 + rr;
            const char* rowb = (char*)sm + S_CAB + row * 3072;
            const uint32_t rowsw = (uint32_t)(row & 7) << 5;
            float total = 0.0f;

            #pragma unroll
            for (int c = 0; c < 2; c++) {
                // --- h build: 16 pairs, each lane does pair (lane&15), d-half (lane>>4) ---
                const int q = c * 16 + (lane & 15);
                int i, j;
                if (q < 30) { i = q / 5; int jj = q % 5; j = jj + (jj >= i ? 1 : 0); }
                else        { i = 0; j = 1; }
                const char* bA = rowb + i * 256;
                const char* bB = rowb + (6 + j) * 256;
                const uint32_t swA = (((uint32_t)(i & 7)) << 4) ^ rowsw;
                const uint32_t swB = (((uint32_t)((6 + j) & 7)) << 4) ^ rowsw;
                const uint32_t dhb = ((uint32_t)(lane >> 4)) * 128;   // f32 byte base
                const uint32_t dhh = ((uint32_t)(lane >> 4)) * 64;    // fp16 byte base

                #pragma unroll
                for (int v = 0; v < 4; v++) {
                    uint32_t hw[4];
                    #pragma unroll
                    for (int h = 0; h < 2; h++) {
                        uint32_t db = dhb + (uint32_t)(v * 2 + h) * 16;
                        float4 a = *reinterpret_cast<const float4*>(bA + (db ^ swA));
                        float4 b = *reinterpret_cast<const float4*>(bB + (db ^ swB));
                        float h0 = softplus_f(a.x + b.x), h1 = softplus_f(a.y + b.y);
                        float h2 = softplus_f(a.z + b.z), h3 = softplus_f(a.w + b.w);
                        hw[h * 2]     = pkhf(h1, h0);
                        hw[h * 2 + 1] = pkhf(h3, h2);
                    }
                    *reinterpret_cast<uint4*>(hp + ((dhh + (uint32_t)v * 16) ^ psw)) =
                        make_uint4(hw[0], hw[1], hw[2], hw[3]);
                }
                __syncwarp();

                // --- M=16 GEMM: 16 MMAs vs register W2 frags ---
                float acc[4][4];
                #pragma unroll
                for (int nt = 0; nt < 4; nt++)
                    #pragma unroll
                    for (int e = 0; e < 4; e++) acc[nt][e] = 0.0f;
                #pragma unroll
                for (int kt = 0; kt < 4; kt++) {
                    uint32_t afr[4];
                    uint32_t adr = hwarp + p15 * 128
                                 + (((uint32_t)kt * 32 + csel) ^ psw);
                    ldsm4(afr, adr);
                    #pragma unroll
                    for (int nt = 0; nt < 4; nt++)
                        mma_f16(acc[nt], afr, B1f[kt][nt][0], B1f[kt][nt][1]);
                }

                // --- epilogue: softplus(t+b2)@W3, mask dummy pairs ---
                #pragma unroll
                for (int hf = 0; hf < 2; hf++) {
                    int prow = c * 16 + (lane >> 2) + hf * 8;
                    if (prow < 30) {
                        float part = 0.0f;
                        #pragma unroll
                        for (int nt = 0; nt < 4; nt++)
                            #pragma unroll
                            for (int e = 0; e < 2; e++) {
                                int nn = nt * 8 + c0 + e;
                                part += softplus_f(acc[nt][hf * 2 + e] + __ldg(b2 + nn))
                                        * __ldg(W3 + nn);
                            }
                        total += part;
                    }
                }
                __syncwarp();   // h buffer safe to overwrite (next chunk/row)
            }

            #pragma unroll
            for (int off = 16; off; off >>= 1)
                total += __shfl_xor_sync(FULLMASK, total, off);
            if (lane == 0)
                out[rbase + row] = 0.5f * total + 15.0f * b3v;
        }
    }
}

extern "C" void kernel_launch(void* const* d_in, const int* in_sizes, int n_in,
                              void* d_out, int out_size) {
    const float* core = (const float*)d_in[0];
    const float* ligs = (const float*)d_in[1];
    const float* W1   = (const float*)d_in[2];
    const float* b1   = (const float*)d_in[3];
    const float* W2   = (const float*)d_in[4];
    const float* b2   = (const float*)d_in[5];
    const float* W3   = (const float*)d_in[6];
    const float* b3   = (const float*)d_in[7];
    float* out = (float*)d_out;

    const int B = in_sizes[0] / 64;   // 32768

    cudaFuncSetAttribute(three_body_kernel,
                         cudaFuncAttributeMaxDynamicSharedMemorySize, SMEM_BYTES);

    // 296 CTAs = 2 per SM target; grid-stride over 2048 groups of 16 rows.
    three_body_kernel<<<296, 256, SMEM_BYTES>>>(
        core, ligs, W1, b1, W2, b2, W3, b3, out, B);
}

// round 11
// speedup vs baseline: 1.2118x; 1.2118x over previous
#include <cuda_runtime.h>
#include <cuda_fp16.h>
#include <cstdint>

// ThreeBodyLayer — round 11: round-9 structure + fp16 numerics, W1 hi-only.
// 192-thr CTAs x2/SM (12 warps/SM), 12-row groups, core GEMM computed once.
// All MMA operands single-product fp16 (x, W1, h, W2): fp16's 2^-11 quant
// error keeps total rel_err ~2e-4 (measured 1.33e-4 with W1 hi+lo in R10).
//
// Phase 1: warp k (0-5) = ligand k as M=16 (12 real + 4 clamped pad rows)
//   @ W1ab^T (n=128); warps 0-3 also take one n16 tile of core proj (+b1).
//   C -> cab[12 rows][13 vecs][64 f32] (256B vec-rows, chunk swizzle).
// Phase 2: warp w rows {2w, 2w+1}; lane p = ordered pair p: h = softplus(
//   cp + A_i + B_j) -> fp16 -> swizzled h buffer; 32 MMAs vs register W2
//   frags; epilogue softplus(t+b2)@W3, dummy mask, shfl reduce.

#define FULLMASK 0xFFFFFFFFu

__device__ __forceinline__ float softplus_f(float x) {
    return fmaxf(x, 0.0f) + __logf(1.0f + __expf(-fabsf(x)));
}
__device__ __forceinline__ uint32_t smem_u32(const void* p) {
    uint32_t a;
    asm("{ .reg .u64 t; cvta.to.shared.u64 t, %1; cvt.u32.u64 %0, t; }"
        : "=r"(a) : "l"(p));
    return a;
}
__device__ __forceinline__ uint32_t pkhf(float a, float b) {   // hi=a, lo=b
    uint32_t r; asm("cvt.rn.f16x2.f32 %0, %1, %2;" : "=r"(r) : "f"(a), "f"(b));
    return r;
}
__device__ __forceinline__ void ldsm4(uint32_t* r, uint32_t addr) {
    asm volatile("ldmatrix.sync.aligned.m8n8.x4.shared.b16 {%0,%1,%2,%3}, [%4];"
                 : "=r"(r[0]), "=r"(r[1]), "=r"(r[2]), "=r"(r[3]) : "r"(addr));
}
__device__ __forceinline__ void mma_f16(float* c, const uint32_t* a,
                                        uint32_t b0, uint32_t b1) {
    asm volatile(
        "mma.sync.aligned.m16n8k16.row.col.f32.f16.f16.f32 "
        "{%0,%1,%2,%3}, {%4,%5,%6,%7}, {%8,%9}, {%0,%1,%2,%3};"
        : "+f"(c[0]), "+f"(c[1]), "+f"(c[2]), "+f"(c[3])
        : "r"(a[0]), "r"(a[1]), "r"(a[2]), "r"(a[3]), "r"(b0), "r"(b1));
}

// ---- SMEM layout (bytes) per 192-thread CTA ----
// W1T: [192 n'][64 k] fp16, 128B rows, chunk xor ((n&7)<<4).
//   n' 0..63: A-proj (W1 rows 64+k), 64..127: B-proj (128+k), 128..191: core (k).
// cab: [12 rows][13 vecs][64 f32], 256B vec-rows, chunk xor ((vec&7)<<4).
// h:   [6 warps][32 pair-rows][64 fp16], 128B rows, chunk xor ((p&7)<<4).
static constexpr int S_W1H = 0;        // 24576
static constexpr int S_CAB = 24576;    // 12*13*256 = 39936
static constexpr int S_H   = 64512;    // 6*4096    = 24576
static constexpr int SMEM_BYTES = 89088;

static constexpr int ROWS_PER_GROUP = 12;

__global__ void __launch_bounds__(192, 2) three_body_kernel(
    const float* __restrict__ core,   // [B, 64]
    const float* __restrict__ ligs,   // [B, 6, 64]
    const float* __restrict__ W1,     // [192, 64]
    const float* __restrict__ b1,     // [64]
    const float* __restrict__ W2,     // [64, 32]
    const float* __restrict__ b2,     // [32]
    const float* __restrict__ W3,     // [32]
    const float* __restrict__ b3,     // [1]
    float* __restrict__ out,          // [B]
    int B)
{
    extern __shared__ unsigned char sm[];
    const uint32_t smem_base = smem_u32(sm);
    const int tid  = threadIdx.x;
    const int lane = tid & 31;
    const int wid  = tid >> 5;        // 0..5

    // ---- stage W1^T (fp16, swizzled 128B rows) ----
    for (int idx = tid; idx < 12288; idx += 192) {
        int n = idx >> 6, k = idx & 63;
        float w;
        if      (n < 64)  w = W1[(64  + k) * 64 + n];
        else if (n < 128) w = W1[(128 + k) * 64 + (n - 64)];
        else              w = W1[k * 64 + (n - 128)];
        int byte = n * 128 + ((2 * k) ^ ((n & 7) << 4));
        *reinterpret_cast<__half*>(sm + S_W1H + byte) = __float2half_rn(w);
    }

    // ---- W2 fragments in registers (fp16, single product) ----
    uint32_t B1f[4][4][2];
    {
        const int krow = (lane & 3) * 2;
        const int ncol = lane >> 2;
        #pragma unroll
        for (int kt = 0; kt < 4; kt++)
            #pragma unroll
            for (int nt = 0; nt < 4; nt++) {
                int k0 = kt * 16 + krow, n = nt * 8 + ncol;
                B1f[kt][nt][0] = pkhf(W2[(k0 + 1) * 32 + n], W2[(k0 + 0) * 32 + n]);
                B1f[kt][nt][1] = pkhf(W2[(k0 + 9) * 32 + n], W2[(k0 + 8) * 32 + n]);
            }
    }
    float b2v[8], w3v[8];
    #pragma unroll
    for (int nt = 0; nt < 4; nt++)
        #pragma unroll
        for (int e = 0; e < 2; e++) {
            int n = nt * 8 + (lane & 3) * 2 + e;
            b2v[nt * 2 + e] = b2[n];
            w3v[nt * 2 + e] = W3[n];
        }
    int pi, pj;
    if (lane < 30) { pi = lane / 5; int jj = lane % 5; pj = jj + (jj >= pi ? 1 : 0); }
    else           { pi = 0; pj = 1; }

    const float b3v = b3[0];
    const int r0  = lane >> 2;            // fragment row in m16 (0..7)
    const int c0  = (lane & 3) * 2;       // fragment col pair base
    const uint32_t lsw  = (uint32_t)(lane & 7) << 4;       // ldsm row swizzle
    const uint32_t csel = (uint32_t)(lane >> 4) * 16;      // 16B sub-chunk
    const uint32_t w1row = (uint32_t)(lane & 15) * 128;
    const uint32_t w1baseH = smem_base + S_W1H;
    const uint32_t hbl  = smem_base + S_H + wid * 4096;
    char* hrow = (char*)sm + S_H + wid * 4096 + lane * 128;
    const uint32_t hsw = (uint32_t)(lane & 7) << 4;

    const int n_groups = (B + ROWS_PER_GROUP - 1) / ROWS_PER_GROUP;   // 2731

    __syncthreads();

    for (int g = blockIdx.x; g < n_groups; g += gridDim.x) {
        const int rbase = g * ROWS_PER_GROUP;
        __syncthreads();   // previous group's phase-2 cab reads complete

        // ================= phase 1: layer-1 GEMMs =================
        {
            // ligand k = wid, M=16 tile (rows 0..11 real, 12..15 pad/clamped)
            const int k  = wid;
            const int ra = rbase + r0;                         // always < B
            const int rb8 = rbase + r0 + 8;
            const int rb = (rb8 < B) ? rb8 : (B - 1);
            const float* xa = ligs + (size_t)ra * 384 + k * 64;
            const float* xb = ligs + (size_t)rb * 384 + k * 64;
            uint32_t af[4][4];
            #pragma unroll
            for (int kt = 0; kt < 4; kt++) {
                int c = kt * 16 + c0;
                float2 x00 = *reinterpret_cast<const float2*>(xa + c);
                float2 x10 = *reinterpret_cast<const float2*>(xb + c);
                float2 x01 = *reinterpret_cast<const float2*>(xa + c + 8);
                float2 x11 = *reinterpret_cast<const float2*>(xb + c + 8);
                af[kt][0] = pkhf(x00.y, x00.x);  af[kt][1] = pkhf(x10.y, x10.x);
                af[kt][2] = pkhf(x01.y, x01.x);  af[kt][3] = pkhf(x11.y, x11.x);
            }
            #pragma unroll
            for (int np = 0; np < 8; np++) {
                float a0[4] = {0.f, 0.f, 0.f, 0.f}, a1[4] = {0.f, 0.f, 0.f, 0.f};
                #pragma unroll
                for (int kt = 0; kt < 4; kt++) {
                    uint32_t bh[4];
                    uint32_t adr = w1baseH + (uint32_t)np * 2048 + w1row
                                 + (((uint32_t)kt * 32 + csel) ^ lsw);
                    ldsm4(bh, adr);
                    mma_f16(a0, af[kt], bh[0], bh[2]);
                    mma_f16(a1, af[kt], bh[1], bh[3]);
                }
                #pragma unroll
                for (int ntl = 0; ntl < 2; ntl++) {
                    const float* a = ntl ? a1 : a0;
                    int n = np * 16 + ntl * 8 + c0;
                    int d = n & 63;
                    int vec = (n < 64) ? k : 6 + k;
                    uint32_t sb = (uint32_t)(d * 4) ^ ((uint32_t)(vec & 7) << 4);
                    char* base = (char*)sm + S_CAB + vec * 256 + sb;
                    *reinterpret_cast<float2*>(base + r0 * 3328) =
                        make_float2(a[0], a[1]);
                    if (r0 < 4)
                        *reinterpret_cast<float2*>(base + (r0 + 8) * 3328) =
                            make_float2(a[2], a[3]);
                }
            }
        }
        if (wid < 4) {
            // core projection (+b1): warp wid owns n-tile np = wid (n = d)
            const int np = wid;
            const int ra = rbase + r0;
            const int rb8 = rbase + r0 + 8;
            const int rb = (rb8 < B) ? rb8 : (B - 1);
            const float* xa = core + (size_t)ra * 64;
            const float* xb = core + (size_t)rb * 64;
            uint32_t af[4][4];
            #pragma unroll
            for (int kt = 0; kt < 4; kt++) {
                int c = kt * 16 + c0;
                float2 x00 = *reinterpret_cast<const float2*>(xa + c);
                float2 x10 = *reinterpret_cast<const float2*>(xb + c);
                float2 x01 = *reinterpret_cast<const float2*>(xa + c + 8);
                float2 x11 = *reinterpret_cast<const float2*>(xb + c + 8);
                af[kt][0] = pkhf(x00.y, x00.x);  af[kt][1] = pkhf(x10.y, x10.x);
                af[kt][2] = pkhf(x01.y, x01.x);  af[kt][3] = pkhf(x11.y, x11.x);
            }
            float a0[4] = {0.f, 0.f, 0.f, 0.f}, a1[4] = {0.f, 0.f, 0.f, 0.f};
            #pragma unroll
            for (int kt = 0; kt < 4; kt++) {
                uint32_t bh[4];
                uint32_t adr = w1baseH + (uint32_t)(128 + np * 16) * 128 + w1row
                             + (((uint32_t)kt * 32 + csel) ^ lsw);
                ldsm4(bh, adr);
                mma_f16(a0, af[kt], bh[0], bh[2]);
                mma_f16(a1, af[kt], bh[1], bh[3]);
            }
            #pragma unroll
            for (int ntl = 0; ntl < 2; ntl++) {
                const float* a = ntl ? a1 : a0;
                int d = np * 16 + ntl * 8 + c0;           // n == d for core
                float bb0 = __ldg(b1 + d), bb1 = __ldg(b1 + d + 1);
                uint32_t sb = (uint32_t)(d * 4) ^ 64u;    // vec 12: (12&7)<<4 = 64
                char* base = (char*)sm + S_CAB + 12 * 256 + sb;
                *reinterpret_cast<float2*>(base + r0 * 3328) =
                    make_float2(a[0] + bb0, a[1] + bb1);
                if (r0 < 4)
                    *reinterpret_cast<float2*>(base + (r0 + 8) * 3328) =
                        make_float2(a[2] + bb0, a[3] + bb1);
            }
        }
        __syncthreads();   // cab complete

        // ================= phase 2: h-build + layer-2 GEMM, 2 rows =================
        #pragma unroll
        for (int rr = 0; rr < 2; rr++) {
            const int row = wid * 2 + rr;
            const char* rowb = (char*)sm + S_CAB + row * 3328;
            const char* baseA = rowb + pi * 256;
            const char* baseB = rowb + (6 + pj) * 256;
            const char* baseC = rowb + 12 * 256;
            const uint32_t vswA = (uint32_t)(pi & 7) << 4;
            const uint32_t vswB = (uint32_t)((6 + pj) & 7) << 4;

            #pragma unroll
            for (int q2 = 0; q2 < 8; q2++) {
                uint32_t hb[4];
                #pragma unroll
                for (int h = 0; h < 2; h++) {
                    uint32_t qb = (uint32_t)(q2 * 2 + h) * 16;
                    float4 a = *reinterpret_cast<const float4*>(baseA + (qb ^ vswA));
                    float4 b = *reinterpret_cast<const float4*>(baseB + (qb ^ vswB));
                    float4 c = *reinterpret_cast<const float4*>(baseC + (qb ^ 64u));
                    float h0 = softplus_f(a.x + b.x + c.x);
                    float h1 = softplus_f(a.y + b.y + c.y);
                    float h2 = softplus_f(a.z + b.z + c.z);
                    float h3 = softplus_f(a.w + b.w + c.w);
                    hb[h * 2]     = pkhf(h1, h0);
                    hb[h * 2 + 1] = pkhf(h3, h2);
                }
                *reinterpret_cast<uint4*>(hrow + (((uint32_t)q2 * 16) ^ hsw)) =
                    make_uint4(hb[0], hb[1], hb[2], hb[3]);
            }
            __syncwarp();

            float acc[2][4][4];
            #pragma unroll
            for (int mt = 0; mt < 2; mt++)
                #pragma unroll
                for (int nt = 0; nt < 4; nt++)
                    #pragma unroll
                    for (int e = 0; e < 4; e++) acc[mt][nt][e] = 0.0f;

            #pragma unroll
            for (int mt = 0; mt < 2; mt++)
                #pragma unroll
                for (int kt = 0; kt < 4; kt++) {
                    uint32_t afr[4];
                    uint32_t adr = hbl + (uint32_t)mt * 2048 + w1row
                                 + (((uint32_t)kt * 32 + csel) ^ lsw);
                    ldsm4(afr, adr);
                    #pragma unroll
                    for (int nt = 0; nt < 4; nt++)
                        mma_f16(acc[mt][nt], afr, B1f[kt][nt][0], B1f[kt][nt][1]);
                }

            // epilogue: y = softplus(t + b2) @ W3, mask dummies, reduce
            float total = 0.0f;
            #pragma unroll
            for (int mt = 0; mt < 2; mt++)
                #pragma unroll
                for (int hf = 0; hf < 2; hf++) {
                    int prow = mt * 16 + (lane >> 2) + hf * 8;
                    float part = 0.0f;
                    #pragma unroll
                    for (int nt = 0; nt < 4; nt++)
                        #pragma unroll
                        for (int e = 0; e < 2; e++)
                            part += softplus_f(acc[mt][nt][hf * 2 + e] + b2v[nt * 2 + e])
                                    * w3v[nt * 2 + e];
                    if (prow < 30) total += part;
                }
            #pragma unroll
            for (int off = 16; off; off >>= 1)
                total += __shfl_xor_sync(FULLMASK, total, off);
            const int gr = rbase + row;
            if (lane == 0 && gr < B)
                out[gr] = 0.5f * total + 15.0f * b3v;
        }
    }
}

extern "C" void kernel_launch(void* const* d_in, const int* in_sizes, int n_in,
                              void* d_out, int out_size) {
    const float* core = (const float*)d_in[0];
    const float* ligs = (const float*)d_in[1];
    const float* W1   = (const float*)d_in[2];
    const float* b1   = (const float*)d_in[3];
    const float* W2   = (const float*)d_in[4];
    const float* b2   = (const float*)d_in[5];
    const float* W3   = (const float*)d_in[6];
    const float* b3   = (const float*)d_in[7];
    float* out = (float*)d_out;

    const int B = in_sizes[0] / 64;   // 32768

    cudaFuncSetAttribute(three_body_kernel,
                         cudaFuncAttributeMaxDynamicSharedMemorySize, SMEM_BYTES);

    // 296 CTAs = 2 per SM (89KB SMEM each); grid-stride over 2731 groups.
    three_body_kernel<<<296, 192, SMEM_BYTES>>>(
        core, ligs, W1, b1, W2, b2, W3, b3, out, B);
}

// round 12
// speedup vs baseline: 1.2655x; 1.0444x over previous
#include <cuda_runtime.h>
#include <cuda_fp16.h>
#include <cstdint>

// ThreeBodyLayer — round 12: software-pipelined phases with double-buffered
// fp16 cab. 192-thr CTAs x2/SM, 12-row groups, fp16 MMA throughout.
// Loop body: sync; phase1(g+1) -> cab[b^1]; phase2(g) <- cab[b].
// One barrier per group; tensor (phase1) and MUFU/FMA (phase2) work from
// different warps interleaves on the SM.
//
// Phase 1: warp k (0-5) = ligand k, M=16 (12 real + 4 clamped pad rows)
//   @ W1ab^T (n=128); warps 0-3 also one n16 tile of core proj (+b1).
//   C -> cab fp16 [12 rows][13 vecs][64], 128B vec-rows,
//   chunk-slot swizzle  slot = (d>>3) ^ ((vec^row)&7)  (store & load
//   conflict-free).
// Phase 2: warp w rows {2w,2w+1}; lane p = ordered pair p: read 3 fp16
//   vecs (uint4 = 8 halves), cvt->f32, h = softplus(A_i+B_j+cp) -> fp16 h
//   buffer; 32 MMAs vs register W2 frags; epilogue softplus(t+b2)@W3.

#define FULLMASK 0xFFFFFFFFu

__device__ __forceinline__ float softplus_f(float x) {
    return fmaxf(x, 0.0f) + __logf(1.0f + __expf(-fabsf(x)));
}
__device__ __forceinline__ uint32_t smem_u32(const void* p) {
    uint32_t a;
    asm("{ .reg .u64 t; cvta.to.shared.u64 t, %1; cvt.u32.u64 %0, t; }"
        : "=r"(a) : "l"(p));
    return a;
}
__device__ __forceinline__ uint32_t pkhf(float a, float b) {   // hi=a, lo=b
    uint32_t r; asm("cvt.rn.f16x2.f32 %0, %1, %2;" : "=r"(r) : "f"(a), "f"(b));
    return r;
}
__device__ __forceinline__ void ldsm4(uint32_t* r, uint32_t addr) {
    asm volatile("ldmatrix.sync.aligned.m8n8.x4.shared.b16 {%0,%1,%2,%3}, [%4];"
                 : "=r"(r[0]), "=r"(r[1]), "=r"(r[2]), "=r"(r[3]) : "r"(addr));
}
__device__ __forceinline__ void mma_f16(float* c, const uint32_t* a,
                                        uint32_t b0, uint32_t b1) {
    asm volatile(
        "mma.sync.aligned.m16n8k16.row.col.f32.f16.f16.f32 "
        "{%0,%1,%2,%3}, {%4,%5,%6,%7}, {%8,%9}, {%0,%1,%2,%3};"
        : "+f"(c[0]), "+f"(c[1]), "+f"(c[2]), "+f"(c[3])
        : "r"(a[0]), "r"(a[1]), "r"(a[2]), "r"(a[3]), "r"(b0), "r"(b1));
}

// ---- SMEM layout (bytes) per 192-thread CTA ----
static constexpr int S_W1H   = 0;        // W1^T fp16 [192 n'][64 k]   24576
static constexpr int S_CAB   = 24576;    // fp16 cab x2 buffers        39936
static constexpr int CAB_BUF = 19968;    //   12 rows * 13 vecs * 128B
static constexpr int S_H     = 64512;    // h: 6 warps x 32x128B       24576
static constexpr int SMEM_BYTES = 89088;

static constexpr int RPG = 12;           // rows per group

__global__ void __launch_bounds__(192, 2) three_body_kernel(
    const float* __restrict__ core,   // [B, 64]
    const float* __restrict__ ligs,   // [B, 6, 64]
    const float* __restrict__ W1,     // [192, 64]
    const float* __restrict__ b1,     // [64]
    const float* __restrict__ W2,     // [64, 32]
    const float* __restrict__ b2,     // [32]
    const float* __restrict__ W3,     // [32]
    const float* __restrict__ b3,     // [1]
    float* __restrict__ out,          // [B]
    int B)
{
    extern __shared__ unsigned char sm[];
    const uint32_t smem_base = smem_u32(sm);
    const int tid  = threadIdx.x;
    const int lane = tid & 31;
    const int wid  = tid >> 5;        // 0..5

    // ---- stage W1^T (fp16, swizzled 128B rows) ----
    for (int idx = tid; idx < 12288; idx += 192) {
        int n = idx >> 6, k = idx & 63;
        float w;
        if      (n < 64)  w = W1[(64  + k) * 64 + n];
        else if (n < 128) w = W1[(128 + k) * 64 + (n - 64)];
        else              w = W1[k * 64 + (n - 128)];
        int byte = n * 128 + ((2 * k) ^ ((n & 7) << 4));
        *reinterpret_cast<__half*>(sm + S_W1H + byte) = __float2half_rn(w);
    }

    // ---- W2 fragments in registers (fp16) ----
    uint32_t B1f[4][4][2];
    {
        const int krow = (lane & 3) * 2;
        const int ncol = lane >> 2;
        #pragma unroll
        for (int kt = 0; kt < 4; kt++)
            #pragma unroll
            for (int nt = 0; nt < 4; nt++) {
                int k0 = kt * 16 + krow, n = nt * 8 + ncol;
                B1f[kt][nt][0] = pkhf(W2[(k0 + 1) * 32 + n], W2[(k0 + 0) * 32 + n]);
                B1f[kt][nt][1] = pkhf(W2[(k0 + 9) * 32 + n], W2[(k0 + 8) * 32 + n]);
            }
    }
    float b2v[8], w3v[8];
    #pragma unroll
    for (int nt = 0; nt < 4; nt++)
        #pragma unroll
        for (int e = 0; e < 2; e++) {
            int n = nt * 8 + (lane & 3) * 2 + e;
            b2v[nt * 2 + e] = b2[n];
            w3v[nt * 2 + e] = W3[n];
        }
    int pi, pj;
    if (lane < 30) { pi = lane / 5; int jj = lane % 5; pj = jj + (jj >= pi ? 1 : 0); }
    else           { pi = 0; pj = 1; }

    const float b3v = b3[0];
    const int r0  = lane >> 2;            // fragment row in m16 (0..7)
    const int c0  = (lane & 3) * 2;       // fragment col pair base
    const uint32_t lsw   = (uint32_t)(lane & 7) << 4;
    const uint32_t csel  = (uint32_t)(lane >> 4) * 16;
    const uint32_t w1row = (uint32_t)(lane & 15) * 128;
    const uint32_t w1baseH = smem_base + S_W1H;
    const uint32_t hbl  = smem_base + S_H + wid * 4096;
    char* hrow = (char*)sm + S_H + wid * 4096 + lane * 128;
    const uint32_t hsw = (uint32_t)(lane & 7) << 4;

    const int n_groups = (B + RPG - 1) / RPG;   // 2731

    // ---- phase 1: layer-1 GEMMs for group at rbase, into cab buffer cb ----
    auto phase1 = [&](int rbase, char* cb) {
        {   // ligand k = wid, M=16 tile (rows 0..11 real, 12..15 clamped)
            const int k  = wid;
            const int ra = rbase + r0;
            const int rb8 = rbase + r0 + 8;
            const int rb = (rb8 < B) ? rb8 : (B - 1);
            const float* xa = ligs + (size_t)ra * 384 + k * 64;
            const float* xb = ligs + (size_t)rb * 384 + k * 64;
            uint32_t af[4][4];
            #pragma unroll
            for (int kt = 0; kt < 4; kt++) {
                int c = kt * 16 + c0;
                float2 x00 = *reinterpret_cast<const float2*>(xa + c);
                float2 x10 = *reinterpret_cast<const float2*>(xb + c);
                float2 x01 = *reinterpret_cast<const float2*>(xa + c + 8);
                float2 x11 = *reinterpret_cast<const float2*>(xb + c + 8);
                af[kt][0] = pkhf(x00.y, x00.x);  af[kt][1] = pkhf(x10.y, x10.x);
                af[kt][2] = pkhf(x01.y, x01.x);  af[kt][3] = pkhf(x11.y, x11.x);
            }
            #pragma unroll
            for (int np = 0; np < 8; np++) {
                float a0[4] = {0.f, 0.f, 0.f, 0.f}, a1[4] = {0.f, 0.f, 0.f, 0.f};
                #pragma unroll
                for (int kt = 0; kt < 4; kt++) {
                    uint32_t bh[4];
                    uint32_t adr = w1baseH + (uint32_t)np * 2048 + w1row
                                 + (((uint32_t)kt * 32 + csel) ^ lsw);
                    ldsm4(bh, adr);
                    mma_f16(a0, af[kt], bh[0], bh[2]);
                    mma_f16(a1, af[kt], bh[1], bh[3]);
                }
                #pragma unroll
                for (int ntl = 0; ntl < 2; ntl++) {
                    const float* a = ntl ? a1 : a0;
                    int n = np * 16 + ntl * 8 + c0;
                    int d = n & 63;
                    int vec = (n < 64) ? k : 6 + k;
                    uint32_t v0 = pkhf(a[1], a[0]);        // lo = d, hi = d+1
                    uint32_t v1 = pkhf(a[3], a[2]);
                    uint32_t off0 = (uint32_t)(2 * d)
                                  ^ ((uint32_t)((vec ^ r0) & 7) << 4);
                    *reinterpret_cast<uint32_t*>(
                        cb + r0 * 1664 + vec * 128 + off0) = v0;
                    if (r0 < 4) {
                        uint32_t off1 = (uint32_t)(2 * d)
                                      ^ ((uint32_t)((vec ^ (r0 + 8)) & 7) << 4);
                        *reinterpret_cast<uint32_t*>(
                            cb + (r0 + 8) * 1664 + vec * 128 + off1) = v1;
                    }
                }
            }
        }
        if (wid < 4) {   // core projection (+b1): n-tile np = wid (n == d)
            const int np = wid;
            const int ra = rbase + r0;
            const int rb8 = rbase + r0 + 8;
            const int rb = (rb8 < B) ? rb8 : (B - 1);
            const float* xa = core + (size_t)ra * 64;
            const float* xb = core + (size_t)rb * 64;
            uint32_t af[4][4];
            #pragma unroll
            for (int kt = 0; kt < 4; kt++) {
                int c = kt * 16 + c0;
                float2 x00 = *reinterpret_cast<const float2*>(xa + c);
                float2 x10 = *reinterpret_cast<const float2*>(xb + c);
                float2 x01 = *reinterpret_cast<const float2*>(xa + c + 8);
                float2 x11 = *reinterpret_cast<const float2*>(xb + c + 8);
                af[kt][0] = pkhf(x00.y, x00.x);  af[kt][1] = pkhf(x10.y, x10.x);
                af[kt][2] = pkhf(x01.y, x01.x);  af[kt][3] = pkhf(x11.y, x11.x);
            }
            float a0[4] = {0.f, 0.f, 0.f, 0.f}, a1[4] = {0.f, 0.f, 0.f, 0.f};
            #pragma unroll
            for (int kt = 0; kt < 4; kt++) {
                uint32_t bh[4];
                uint32_t adr = w1baseH + (uint32_t)(128 + np * 16) * 128 + w1row
                             + (((uint32_t)kt * 32 + csel) ^ lsw);
                ldsm4(bh, adr);
                mma_f16(a0, af[kt], bh[0], bh[2]);
                mma_f16(a1, af[kt], bh[1], bh[3]);
            }
            #pragma unroll
            for (int ntl = 0; ntl < 2; ntl++) {
                const float* a = ntl ? a1 : a0;
                int d = np * 16 + ntl * 8 + c0;
                float bb0 = __ldg(b1 + d), bb1 = __ldg(b1 + d + 1);
                uint32_t v0 = pkhf(a[1] + bb1, a[0] + bb0);
                uint32_t v1 = pkhf(a[3] + bb1, a[2] + bb0);
                uint32_t off0 = (uint32_t)(2 * d)
                              ^ ((uint32_t)((12 ^ r0) & 7) << 4);
                *reinterpret_cast<uint32_t*>(
                    cb + r0 * 1664 + 12 * 128 + off0) = v0;
                if (r0 < 4) {
                    uint32_t off1 = (uint32_t)(2 * d)
                                  ^ ((uint32_t)((12 ^ (r0 + 8)) & 7) << 4);
                    *reinterpret_cast<uint32_t*>(
                        cb + (r0 + 8) * 1664 + 12 * 128 + off1) = v1;
                }
            }
        }
    };

    // ---- phase 2: h-build + layer-2 GEMM + epilogue for group at rbase ----
    auto phase2 = [&](int rbase, const char* cb) {
        #pragma unroll
        for (int rr = 0; rr < 2; rr++) {
            const int row = wid * 2 + rr;
            const char* rowb = cb + row * 1664;
            const char* bA = rowb + pi * 128;
            const char* bB = rowb + (6 + pj) * 128;
            const char* bC = rowb + 12 * 128;
            const uint32_t swA = (uint32_t)((pi ^ row) & 7) << 4;
            const uint32_t swB = (uint32_t)(((6 + pj) ^ row) & 7) << 4;
            const uint32_t swC = (uint32_t)((12 ^ row) & 7) << 4;

            #pragma unroll
            for (int q2 = 0; q2 < 8; q2++) {
                const uint32_t qb = (uint32_t)q2 * 16;
                uint4 ua = *reinterpret_cast<const uint4*>(bA + (qb ^ swA));
                uint4 ub = *reinterpret_cast<const uint4*>(bB + (qb ^ swB));
                uint4 uc = *reinterpret_cast<const uint4*>(bC + (qb ^ swC));
                const __half2* ha = reinterpret_cast<const __half2*>(&ua);
                const __half2* hb2 = reinterpret_cast<const __half2*>(&ub);
                const __half2* hc = reinterpret_cast<const __half2*>(&uc);
                uint32_t hw[4];
                #pragma unroll
                for (int w = 0; w < 4; w++) {
                    float2 fa = __half22float2(ha[w]);
                    float2 fb = __half22float2(hb2[w]);
                    float2 fc = __half22float2(hc[w]);
                    float s0 = fa.x + fb.x + fc.x;
                    float s1 = fa.y + fb.y + fc.y;
                    hw[w] = pkhf(softplus_f(s1), softplus_f(s0));
                }
                *reinterpret_cast<uint4*>(hrow + (qb ^ hsw)) =
                    make_uint4(hw[0], hw[1], hw[2], hw[3]);
            }
            __syncwarp();

            float acc[2][4][4];
            #pragma unroll
            for (int mt = 0; mt < 2; mt++)
                #pragma unroll
                for (int nt = 0; nt < 4; nt++)
                    #pragma unroll
                    for (int e = 0; e < 4; e++) acc[mt][nt][e] = 0.0f;

            #pragma unroll
            for (int mt = 0; mt < 2; mt++)
                #pragma unroll
                for (int kt = 0; kt < 4; kt++) {
                    uint32_t afr[4];
                    uint32_t adr = hbl + (uint32_t)mt * 2048 + w1row
                                 + (((uint32_t)kt * 32 + csel) ^ lsw);
                    ldsm4(afr, adr);
                    #pragma unroll
                    for (int nt = 0; nt < 4; nt++)
                        mma_f16(acc[mt][nt], afr, B1f[kt][nt][0], B1f[kt][nt][1]);
                }

            float total = 0.0f;
            #pragma unroll
            for (int mt = 0; mt < 2; mt++)
                #pragma unroll
                for (int hf = 0; hf < 2; hf++) {
                    int prow = mt * 16 + (lane >> 2) + hf * 8;
                    float part = 0.0f;
                    #pragma unroll
                    for (int nt = 0; nt < 4; nt++)
                        #pragma unroll
                        for (int e = 0; e < 2; e++)
                            part += softplus_f(acc[mt][nt][hf * 2 + e] + b2v[nt * 2 + e])
                                    * w3v[nt * 2 + e];
                    if (prow < 30) total += part;
                }
            #pragma unroll
            for (int off = 16; off; off >>= 1)
                total += __shfl_xor_sync(FULLMASK, total, off);
            const int gr = rbase + row;
            if (lane == 0 && gr < B)
                out[gr] = 0.5f * total + 15.0f * b3v;
            __syncwarp();   // h buffer free before next row overwrites it
        }
    };

    __syncthreads();   // W1 staged

    // ---- pipelined main loop: 1 barrier per group ----
    char* cab = (char*)sm + S_CAB;
    int g = blockIdx.x;
    if (g < n_groups) phase1(g * RPG, cab);         // prologue -> buffer 0
    int it = 0;
    for (; g < n_groups; g += gridDim.x, it++) {
        __syncthreads();   // prev phase1 (buf it&1) + prev phase2 (buf (it+1)&1) done
        int gn = g + gridDim.x;
        if (gn < n_groups) phase1(gn * RPG, cab + ((it + 1) & 1) * CAB_BUF);
        phase2(g * RPG, cab + (it & 1) * CAB_BUF);
    }
}

extern "C" void kernel_launch(void* const* d_in, const int* in_sizes, int n_in,
                              void* d_out, int out_size) {
    const float* core = (const float*)d_in[0];
    const float* ligs = (const float*)d_in[1];
    const float* W1   = (const float*)d_in[2];
    const float* b1   = (const float*)d_in[3];
    const float* W2   = (const float*)d_in[4];
    const float* b2   = (const float*)d_in[5];
    const float* W3   = (const float*)d_in[6];
    const float* b3   = (const float*)d_in[7];
    float* out = (float*)d_out;

    const int B = in_sizes[0] / 64;   // 32768

    cudaFuncSetAttribute(three_body_kernel,
                         cudaFuncAttributeMaxDynamicSharedMemorySize, SMEM_BYTES);

    // 296 CTAs = 2 per SM (89KB SMEM each); grid-stride over 2731 groups.
    three_body_kernel<<<296, 192, SMEM_BYTES>>>(
        core, ligs, W1, b1, W2, b2, W3, b3, out, B);
}